// round 2
// baseline (speedup 1.0000x reference)
#include <cuda_runtime.h>
#include <cstdint>

// FastVCompressor: nearest-codebook VQ of keys/values.
//   keys   [4,4096,1024] f32   = d_in[0]
//   values [4,4096,1024] f32   = d_in[1]
//   codebook [256,1024]  f32   = d_in[2]
//   out = keys_c (16M floats) ++ values_c (16M floats)
//
// argmin_c ( ||c||^2 - 2 x.c )  == reference argmin of full squared distance.

#define TM   64          // rows per block
#define BK   16          // K-chunk
#define XPAD 68          // Xs row pad (16B-aligned vector loads, 2-way STS conflicts)
#define CPAD 260         // Cs row pad (16B-aligned vector loads, 2-way STS conflicts)
#define NROWS_HALF 16384 // rows per tensor
#define H    1024
#define C    256

__device__ float g_csq[C];

// ---------------------------------------------------------------- c_sq
__global__ void csq_kernel(const float* __restrict__ cb) {
    const int c = blockIdx.x;
    const float4 v = ((const float4*)(cb + (size_t)c * H))[threadIdx.x]; // 256 thr * 4 = 1024
    float s = v.x * v.x + v.y * v.y + v.z * v.z + v.w * v.w;
    #pragma unroll
    for (int o = 16; o; o >>= 1) s += __shfl_xor_sync(0xffffffffu, s, o);
    __shared__ float ws[8];
    if ((threadIdx.x & 31) == 0) ws[threadIdx.x >> 5] = s;
    __syncthreads();
    if (threadIdx.x == 0) {
        float t = 0.f;
        #pragma unroll
        for (int i = 0; i < 8; ++i) t += ws[i];
        g_csq[c] = t;
    }
}

// ---------------------------------------------------------------- main VQ
__global__ __launch_bounds__(256, 2) void vq_kernel(
    const float* __restrict__ keys, const float* __restrict__ values,
    const float* __restrict__ cb, float* __restrict__ out)
{
    __shared__ float Xs[BK][XPAD];   // [k][row]  (transposed)
    __shared__ float Cs[BK][CPAD];   // [k][code] (transposed)

    const int tid = threadIdx.x;
    const int tr  = tid >> 5;        // 0..7  : row group (== warp id)
    const int tc  = tid & 31;        // 0..31 : code group (== lane)
    const int bid = blockIdx.x;

    const float* src = (bid < 256)
        ? (keys   + (size_t)bid         * TM * H)
        : (values + (size_t)(bid - 256) * TM * H);

    // global-load mapping: k4 = float4 slot within BK, lrow = row/code id
    const int k4   = tid & 3;        // k offset = k4*4
    const int lrow = tid >> 2;       // 0..63

    unsigned long long acc[8][4];    // 8 rows x 4 code-pairs (f32x2)
    #pragma unroll
    for (int r = 0; r < 8; ++r)
        #pragma unroll
        for (int j = 0; j < 4; ++j) acc[r][j] = 0ull;

    float4 xr;        // X prefetch: 1 float4 (row lrow)
    float4 cr[4];     // C prefetch: codes lrow + 64*i

    // preload tile 0
    xr = *((const float4*)(src + (size_t)lrow * H) + k4);
    #pragma unroll
    for (int i = 0; i < 4; ++i)
        cr[i] = *((const float4*)(cb + (size_t)(lrow + 64 * i) * H) + k4);

    const int NT = H / BK;
    for (int t = 0; t < NT; ++t) {
        __syncthreads();
        // commit prefetched tile to smem (transposed)
        #pragma unroll
        for (int j = 0; j < 4; ++j)
            Xs[k4 * 4 + j][lrow] = ((const float*)&xr)[j];
        #pragma unroll
        for (int i = 0; i < 4; ++i)
            #pragma unroll
            for (int j = 0; j < 4; ++j)
                Cs[k4 * 4 + j][lrow + 64 * i] = ((const float*)&cr[i])[j];
        __syncthreads();

        if (t + 1 < NT) {   // prefetch next tile (overlaps compute below)
            const int k0 = (t + 1) * BK;
            xr = *((const float4*)(src + (size_t)lrow * H + k0) + k4);
            #pragma unroll
            for (int i = 0; i < 4; ++i)
                cr[i] = *((const float4*)(cb + (size_t)(lrow + 64 * i) * H + k0) + k4);
        }

        #pragma unroll
        for (int k = 0; k < BK; ++k) {
            const float4 xa = *(const float4*)&Xs[k][tr * 8];
            const float4 xb = *(const float4*)&Xs[k][tr * 8 + 4];
            const ulonglong2 c01 = *(const ulonglong2*)&Cs[k][tc * 8];
            const ulonglong2 c23 = *(const ulonglong2*)&Cs[k][tc * 8 + 4];
            const unsigned long long cp0 = c01.x, cp1 = c01.y,
                                     cp2 = c23.x, cp3 = c23.y;
            const float xv[8] = {xa.x, xa.y, xa.z, xa.w, xb.x, xb.y, xb.z, xb.w};
            #pragma unroll
            for (int r = 0; r < 8; ++r) {
                unsigned long long xd;
                asm("mov.b64 %0, {%1, %1};" : "=l"(xd)
                    : "r"(__float_as_uint(xv[r])));
                asm("fma.rn.f32x2 %0, %1, %2, %0;" : "+l"(acc[r][0]) : "l"(cp0), "l"(xd));
                asm("fma.rn.f32x2 %0, %1, %2, %0;" : "+l"(acc[r][1]) : "l"(cp1), "l"(xd));
                asm("fma.rn.f32x2 %0, %1, %2, %0;" : "+l"(acc[r][2]) : "l"(cp2), "l"(xd));
                asm("fma.rn.f32x2 %0, %1, %2, %0;" : "+l"(acc[r][3]) : "l"(cp3), "l"(xd));
            }
        }
    }

    // ---------------- epilogue: per-row argmin of (csq - 2*dot), gather, write
    #pragma unroll 1
    for (int r = 0; r < 8; ++r) {
        float best = 3.4e38f;
        int bi = 0;
        #pragma unroll
        for (int j = 0; j < 4; ++j) {
            const int c0 = tc * 8 + 2 * j;
            const float lo = __uint_as_float((unsigned)(acc[r][j]));
            const float hi = __uint_as_float((unsigned)(acc[r][j] >> 32));
            const float d0 = g_csq[c0]     - 2.0f * lo;
            const float d1 = g_csq[c0 + 1] - 2.0f * hi;
            if (d0 < best) { best = d0; bi = c0; }
            if (d1 < best) { best = d1; bi = c0 + 1; }
        }
        // warp reduce, first-index tie-break (matches jnp.argmin)
        #pragma unroll
        for (int o = 16; o; o >>= 1) {
            const float ov = __shfl_xor_sync(0xffffffffu, best, o);
            const int   oi = __shfl_xor_sync(0xffffffffu, bi, o);
            if (ov < best || (ov == best && oi < bi)) { best = ov; bi = oi; }
        }
        const size_t row = (size_t)bid * TM + tr * 8 + r;
        const float scale = (g_csq[bi] > 0.01f) ? 1.0f : 0.0f;  // ||c||>0.1
        const float4* cbr = (const float4*)(cb + (size_t)bi * H);
        float4* o4 = (float4*)(out + row * H);
        #pragma unroll
        for (int j = tc; j < H / 4; j += 32) {
            float4 v = __ldg(cbr + j);
            v.x *= scale; v.y *= scale; v.z *= scale; v.w *= scale;
            o4[j] = v;
        }
    }
}

// ---------------------------------------------------------------- launch
extern "C" void kernel_launch(void* const* d_in, const int* in_sizes, int n_in,
                              void* d_out, int out_size) {
    const float* keys     = (const float*)d_in[0];
    const float* values   = (const float*)d_in[1];
    const float* codebook = (const float*)d_in[2];
    float* out = (float*)d_out;
    (void)in_sizes; (void)n_in; (void)out_size;

    csq_kernel<<<C, 256>>>(codebook);
    vq_kernel<<<2 * NROWS_HALF / TM, 256>>>(keys, values, codebook, out);
}

// round 6
// speedup vs baseline: 1.2094x; 1.2094x over previous
#include <cuda_runtime.h>
#include <cuda_bf16.h>
#include <cstdint>

// FastVCompressor via mma.sync (HMMA, bf16 3-way exact split, 6 products).
// v3: cp.async.bulk+mbarrier pipeline replaced by cp.async.cg (LDGSTS) +
// commit/wait groups — suspected runtime hang of bulk-DMA on bare sm_103
// (two container timeouts with zero harness output).
//   D[row, code] = dot(X_row, C_code); argmin_c (||c||^2 - 2 dot)
//   keys   [4,4096,1024] f32 = d_in[0]
//   values [4,4096,1024] f32 = d_in[1]
//   codebook [256,1024]  f32 = d_in[2]
//   out = keys_c ++ values_c (32M floats)

#define H      1024
#define CODES  256
#define MROWS  64          // rows per CTA
#define NKC    64          // k16 chunks (1024/16)
#define SPLITB 12288       // one split, one chunk: 256 codes * 48B (padded)
#define BUFB   (3 * SPLITB)    // 36864

// ---- smem layout ----
#define SO_IDX   64                      // 64 ints
#define SO_CBUF  1024                    // 2 * BUFB = 73728 (epilogue Ds overlays)
#define SO_XS    (SO_CBUF + 2 * BUFB)    // 74752: Xs[2][64][20] f32 = 10240
#define XS_HALF  1280                    // 64*20 floats
#define SO_CSQ   (SO_XS + 10240)         // 84992: 256 floats
#define SMEM_TOTAL (SO_CSQ + 1024)       // 86016
#define DS_STRIDE 264

__device__ float g_csq[CODES];
__device__ __align__(128) unsigned char g_bsplit[NKC * BUFB];   // 2.25MB

// ---------------------------------------------------------------- helpers
static __device__ __forceinline__ uint32_t smem_u32(const void* p) {
    uint32_t a;
    asm("{ .reg .u64 t; cvta.to.shared.u64 t, %1; cvt.u32.u64 %0, t; }"
        : "=r"(a) : "l"(p));
    return a;
}

#define CPA16(dst, src) \
    asm volatile("cp.async.cg.shared.global [%0], [%1], 16;" \
                 :: "r"(dst), "l"(src) : "memory")
#define CPA_COMMIT() asm volatile("cp.async.commit_group;" ::: "memory")
#define CPA_WAIT(n)  asm volatile("cp.async.wait_group %0;" :: "n"(n) : "memory")

#define LDSM4(r0, r1, r2, r3, addr)                                             \
    asm volatile("ldmatrix.sync.aligned.m8n8.x4.shared.b16 {%0,%1,%2,%3}, [%4];" \
        : "=r"(r0), "=r"(r1), "=r"(r2), "=r"(r3) : "r"(addr))

#define MMA4(c, a0, a1, a2, a3, b0, b1)                                         \
    asm volatile("mma.sync.aligned.m16n8k16.row.col.f32.bf16.bf16.f32 "         \
        "{%0,%1,%2,%3}, {%4,%5,%6,%7}, {%8,%9}, {%0,%1,%2,%3};"                 \
        : "+f"((c)[0]), "+f"((c)[1]), "+f"((c)[2]), "+f"((c)[3])                \
        : "r"(a0), "r"(a1), "r"(a2), "r"(a3), "r"(b0), "r"(b1))

#define CVT2(d, hi, lo) \
    asm("cvt.rn.bf16x2.f32 %0, %1, %2;" : "=r"(d) : "f"(hi), "f"(lo))

// one product: A-split regs AS[16], B-split at byte offset soff in current buf
#define PRODUCT(AS, soff) do {                                                  \
    uint32_t b0, b1, b2, b3, b4, b5, b6, b7;                                    \
    LDSM4(b0, b1, b2, b3, bb + (soff) + 0 * 768 + laneoff);                     \
    LDSM4(b4, b5, b6, b7, bb + (soff) + 1 * 768 + laneoff);                     \
    _Pragma("unroll")                                                           \
    for (int _mt = 0; _mt < 4; ++_mt) {                                         \
        MMA4(acc[_mt][0], AS[_mt*4+0], AS[_mt*4+1], AS[_mt*4+2], AS[_mt*4+3], b0, b1); \
        MMA4(acc[_mt][1], AS[_mt*4+0], AS[_mt*4+1], AS[_mt*4+2], AS[_mt*4+3], b2, b3); \
        MMA4(acc[_mt][2], AS[_mt*4+0], AS[_mt*4+1], AS[_mt*4+2], AS[_mt*4+3], b4, b5); \
        MMA4(acc[_mt][3], AS[_mt*4+0], AS[_mt*4+1], AS[_mt*4+2], AS[_mt*4+3], b6, b7); \
    }                                                                           \
} while (0)

// ---------------------------------------------------------------- prep: c_sq
__global__ void csq_kernel(const float* __restrict__ cb) {
    const int c = blockIdx.x;
    const float4 v = ((const float4*)(cb + (size_t)c * H))[threadIdx.x];
    float s = v.x * v.x + v.y * v.y + v.z * v.z + v.w * v.w;
    #pragma unroll
    for (int o = 16; o; o >>= 1) s += __shfl_xor_sync(0xffffffffu, s, o);
    __shared__ float ws[8];
    if ((threadIdx.x & 31) == 0) ws[threadIdx.x >> 5] = s;
    __syncthreads();
    if (threadIdx.x == 0) {
        float t = 0.f;
        #pragma unroll
        for (int i = 0; i < 8; ++i) t += ws[i];
        g_csq[c] = t;
    }
}

// ------------------------------------------- prep: codebook 3-split, padded rows
__global__ void bprep_kernel(const float* __restrict__ cb) {
    const int code = blockIdx.x;
    const float4 v = ((const float4*)(cb + (size_t)code * H))[threadIdx.x];
    const float f[4] = {v.x, v.y, v.z, v.w};
    #pragma unroll
    for (int e = 0; e < 4; ++e) {
        const int k = threadIdx.x * 4 + e;
        const float x = f[e];
        const __nv_bfloat16 hb = __float2bfloat16(x);
        const float r1 = x - __bfloat162float(hb);
        const __nv_bfloat16 mb = __float2bfloat16(r1);
        const __nv_bfloat16 lb = __float2bfloat16(r1 - __bfloat162float(mb));
        unsigned char* base = g_bsplit + (size_t)(k >> 4) * BUFB + code * 48 + (k & 15) * 2;
        *(__nv_bfloat16*)(base)              = hb;
        *(__nv_bfloat16*)(base + SPLITB)     = mb;
        *(__nv_bfloat16*)(base + 2 * SPLITB) = lb;
    }
}

// ---------------------------------------------------------------- main VQ
__global__ __launch_bounds__(256, 1) void vq_kernel(
    const float* __restrict__ keys, const float* __restrict__ values,
    const float* __restrict__ cb, float* __restrict__ out)
{
    extern __shared__ char smem[];
    const uint32_t sb = smem_u32(smem);
    const int tid = threadIdx.x, lane = tid & 31, nw = tid >> 5;
    const int bid = blockIdx.x;

    const float* src = (bid < 256) ? keys   + (size_t)bid * MROWS * H
                                   : values + (size_t)(bid - 256) * MROWS * H;

    float* Xs = (float*)(smem + SO_XS);
    const int xrow = tid >> 2, xc4 = (tid & 3) * 4;

    // preload X chunk 0 -> Xs[0]
    {
        const float4 v = *(const float4*)(src + (size_t)xrow * H + xc4);
        *(float4*)&Xs[xrow * 20 + xc4] = v;
    }
    // preload B chunk 0 -> cbuf0 (9 x 16B per thread)
    #pragma unroll
    for (int j = 0; j < 9; ++j) {
        const uint32_t o = (uint32_t)(tid + 256 * j) * 16u;
        CPA16(sb + SO_CBUF + o, g_bsplit + o);
    }
    CPA_COMMIT();

    float acc[4][4][4];
    #pragma unroll
    for (int a = 0; a < 4; ++a)
        #pragma unroll
        for (int b = 0; b < 4; ++b)
            #pragma unroll
            for (int c = 0; c < 4; ++c) acc[a][b][c] = 0.f;

    const uint32_t laneoff = (uint32_t)nw * 1536u
        + (uint32_t)((lane & 7) + ((lane >> 4) << 3)) * 48u
        + (uint32_t)((lane >> 3) & 1) * 16u;
    const int r0 = lane >> 2, c0 = (lane & 3) * 2;

    for (int kc = 0; kc < NKC; ++kc) {
        const int b = kc & 1;
        __syncthreads();   // prev-iter reads of cbuf[b^1] / Xs writes complete

        if (kc + 1 < NKC) {
            // B chunk kc+1 -> other buffer (all threads)
            const unsigned char* sg = g_bsplit + (size_t)(kc + 1) * BUFB;
            const uint32_t dstb = sb + SO_CBUF + (uint32_t)(b ^ 1) * BUFB;
            #pragma unroll
            for (int j = 0; j < 9; ++j) {
                const uint32_t o = (uint32_t)(tid + 256 * j) * 16u;
                CPA16(dstb + o, sg + o);
            }
            CPA_COMMIT();
            // X chunk kc+1 -> Xs[b^1]
            const float4 v = *(const float4*)(src + (size_t)xrow * H + (kc + 1) * 16 + xc4);
            *(float4*)&Xs[(b ^ 1) * XS_HALF + xrow * 20 + xc4] = v;
        }

        if (kc + 1 < NKC) CPA_WAIT(1); else CPA_WAIT(0);
        __syncthreads();   // cbuf[b] fully resident for all threads

        // exact 3-way bf16 split of X chunk kc -> A fragments (registers)
        uint32_t ah[16], am[16], al[16];
        const float* xbuf = &Xs[b * XS_HALF];
        #pragma unroll
        for (int mt = 0; mt < 4; ++mt)
            #pragma unroll
            for (int i = 0; i < 4; ++i) {
                const int rr = mt * 16 + r0 + (i & 1) * 8;
                const float2 v = *(const float2*)&xbuf[rr * 20 + c0 + (i >> 1) * 8];
                float vx = v.x, vy = v.y;
                uint32_t h_; CVT2(h_, vy, vx);
                vx -= __uint_as_float(h_ << 16);
                vy -= __uint_as_float(h_ & 0xffff0000u);
                uint32_t m_; CVT2(m_, vy, vx);
                vx -= __uint_as_float(m_ << 16);
                vy -= __uint_as_float(m_ & 0xffff0000u);
                uint32_t l_; CVT2(l_, vy, vx);
                ah[mt * 4 + i] = h_; am[mt * 4 + i] = m_; al[mt * 4 + i] = l_;
            }

        const uint32_t bb = sb + SO_CBUF + (uint32_t)b * BUFB;
        PRODUCT(ah, 0);          // hh
        PRODUCT(ah, SPLITB);     // hm
        PRODUCT(am, 0);          // mh
        PRODUCT(am, SPLITB);     // mm
        PRODUCT(ah, 2 * SPLITB); // hl
        PRODUCT(al, 0);          // lh
    }

    // ---------------- epilogue ----------------
    __syncthreads();
    float* Ds = (float*)(smem + SO_CBUF);        // overlays B buffers
    #pragma unroll
    for (int mt = 0; mt < 4; ++mt)
        #pragma unroll
        for (int nt = 0; nt < 4; ++nt) {
            const int r = mt * 16 + r0;
            const int c = nw * 32 + nt * 8 + c0;
            *(float2*)&Ds[r * DS_STRIDE + c]       = make_float2(acc[mt][nt][0], acc[mt][nt][1]);
            *(float2*)&Ds[(r + 8) * DS_STRIDE + c] = make_float2(acc[mt][nt][2], acc[mt][nt][3]);
        }
    ((float*)(smem + SO_CSQ))[tid] = g_csq[tid];
    __syncthreads();

    int* idxs = (int*)(smem + SO_IDX);
    const float* csq_s = (const float*)(smem + SO_CSQ);
    if (tid < MROWS) {
        const float* row = &Ds[tid * DS_STRIDE];
        float best = 3.4e38f;
        int bi = 0;
        for (int c = 0; c < CODES; ++c) {
            const float d = csq_s[c] - 2.0f * row[c];
            if (d < best) { best = d; bi = c; }   // first-index tie-break
        }
        idxs[tid] = bi;
    }
    __syncthreads();

    // gather winning codebook rows, apply sparsity mask, write coalesced
    const float4* cb4 = (const float4*)cb;
    float4* o4 = (float4*)out + (size_t)bid * MROWS * (H / 4);
    for (int r = 0; r < MROWS; ++r) {
        const int idx = idxs[r];
        const float sc = (csq_s[idx] > 0.01f) ? 1.0f : 0.0f;   // ||c|| > 0.1
        float4 v = cb4[(size_t)idx * (H / 4) + tid];
        v.x *= sc; v.y *= sc; v.z *= sc; v.w *= sc;
        o4[(size_t)r * (H / 4) + tid] = v;
    }
}

// ---------------------------------------------------------------- launch
extern "C" void kernel_launch(void* const* d_in, const int* in_sizes, int n_in,
                              void* d_out, int out_size) {
    const float* keys     = (const float*)d_in[0];
    const float* values   = (const float*)d_in[1];
    const float* codebook = (const float*)d_in[2];
    float* out = (float*)d_out;
    (void)in_sizes; (void)n_in; (void)out_size;

    cudaFuncSetAttribute(vq_kernel, cudaFuncAttributeMaxDynamicSharedMemorySize, SMEM_TOTAL);
    csq_kernel<<<CODES, 256>>>(codebook);
    bprep_kernel<<<CODES, 256>>>(codebook);
    vq_kernel<<<512, 256, SMEM_TOTAL>>>(keys, values, codebook, out);
}

// round 7
// speedup vs baseline: 3.2547x; 2.6912x over previous
#include <cuda_runtime.h>
#include <cuda_bf16.h>
#include <cstdint>

// FastVCompressor v4: bf16 HMMA *screening* (hh product only) + exact fp32
// rescoring of near-min candidates.  argmin_c (||c||^2 - 2 x.c).
//   keys   [4,4096,1024] f32 = d_in[0]
//   values [4,4096,1024] f32 = d_in[1]
//   codebook [256,1024]  f32 = d_in[2]
//   out = keys_c ++ values_c (32M floats)

#define H      1024
#define CODES  256
#define MROWS  64          // rows per CTA
#define NKC    64          // k16 chunks
#define BUFB   12288       // one chunk of bf16-hi codebook: 256 codes * 48B
#define NCAND  24
#define MARGIN 2.0f        // ~25 sigma of screening error

// ---- smem layout ----
#define SO_IDX    0                      // 64 ints: final winner per row
#define SO_CNT    256                    // 64 ints: candidate counts
#define SO_RMIN   512                    // 64 floats: screened min per row
#define SO_CSQ    768                    // 256 floats
#define SO_WVAL   1792                   // 64*8 floats: per-warp row mins
#define SO_CAND   3840                   // 64*24 ints = 6144
#define SO_CBUF   9984                   // 2*BUFB = 24576 (128B aligned)
#define SO_XS     34560                  // Xs[2][64][20] f32 = 10240
#define XS_HALF   1280
#define SMEM_TOTAL 44800

__device__ float g_csq[CODES];
__device__ __align__(128) unsigned char g_bsplit[NKC * BUFB];   // 768 KB (L2-resident)

// ---------------------------------------------------------------- helpers
static __device__ __forceinline__ uint32_t smem_u32(const void* p) {
    uint32_t a;
    asm("{ .reg .u64 t; cvta.to.shared.u64 t, %1; cvt.u32.u64 %0, t; }"
        : "=r"(a) : "l"(p));
    return a;
}

#define CPA16(dst, src) \
    asm volatile("cp.async.cg.shared.global [%0], [%1], 16;" \
                 :: "r"(dst), "l"(src) : "memory")
#define CPA_COMMIT() asm volatile("cp.async.commit_group;" ::: "memory")
#define CPA_WAIT(n)  asm volatile("cp.async.wait_group %0;" :: "n"(n) : "memory")

#define LDSM4(r0, r1, r2, r3, addr)                                             \
    asm volatile("ldmatrix.sync.aligned.m8n8.x4.shared.b16 {%0,%1,%2,%3}, [%4];" \
        : "=r"(r0), "=r"(r1), "=r"(r2), "=r"(r3) : "r"(addr))

#define MMA4(c, a0, a1, a2, a3, b0, b1)                                         \
    asm volatile("mma.sync.aligned.m16n8k16.row.col.f32.bf16.bf16.f32 "         \
        "{%0,%1,%2,%3}, {%4,%5,%6,%7}, {%8,%9}, {%0,%1,%2,%3};"                 \
        : "+f"((c)[0]), "+f"((c)[1]), "+f"((c)[2]), "+f"((c)[3])                \
        : "r"(a0), "r"(a1), "r"(a2), "r"(a3), "r"(b0), "r"(b1))

#define CVT2(d, hi, lo) \
    asm("cvt.rn.bf16x2.f32 %0, %1, %2;" : "=r"(d) : "f"(hi), "f"(lo))

// ---------------------------------------------------------------- prep: c_sq
__global__ void csq_kernel(const float* __restrict__ cb) {
    const int c = blockIdx.x;
    const float4 v = ((const float4*)(cb + (size_t)c * H))[threadIdx.x];
    float s = v.x * v.x + v.y * v.y + v.z * v.z + v.w * v.w;
    #pragma unroll
    for (int o = 16; o; o >>= 1) s += __shfl_xor_sync(0xffffffffu, s, o);
    __shared__ float ws[8];
    if ((threadIdx.x & 31) == 0) ws[threadIdx.x >> 5] = s;
    __syncthreads();
    if (threadIdx.x == 0) {
        float t = 0.f;
        #pragma unroll
        for (int i = 0; i < 8; ++i) t += ws[i];
        g_csq[c] = t;
    }
}

// ------------------------------------------- prep: codebook bf16-hi, 48B rows
__global__ void bprep_kernel(const float* __restrict__ cb) {
    const int code = blockIdx.x;
    const float4 v = ((const float4*)(cb + (size_t)code * H))[threadIdx.x];
    const float f[4] = {v.x, v.y, v.z, v.w};
    #pragma unroll
    for (int e = 0; e < 4; ++e) {
        const int k = threadIdx.x * 4 + e;
        *(__nv_bfloat16*)(g_bsplit + (size_t)(k >> 4) * BUFB + code * 48 + (k & 15) * 2)
            = __float2bfloat16(f[e]);
    }
}

// ---------------------------------------------------------------- main VQ
__global__ __launch_bounds__(256, 2) void vq_kernel(
    const float* __restrict__ keys, const float* __restrict__ values,
    const float* __restrict__ cb, float* __restrict__ out)
{
    extern __shared__ char smem[];
    const uint32_t sb = smem_u32(smem);
    const int tid = threadIdx.x, lane = tid & 31, nw = tid >> 5;
    const int bid = blockIdx.x;

    const float* src = (bid < 256) ? keys   + (size_t)bid * MROWS * H
                                   : values + (size_t)(bid - 256) * MROWS * H;

    float* Xs = (float*)(smem + SO_XS);
    const int xrow = tid >> 2, xc4 = (tid & 3) * 4;

    // preload X chunk 0 -> Xs[0]
    {
        const float4 v = *(const float4*)(src + (size_t)xrow * H + xc4);
        *(float4*)&Xs[xrow * 20 + xc4] = v;
    }
    // preload B chunk 0 -> cbuf0 (3 x 16B per thread)
    #pragma unroll
    for (int j = 0; j < 3; ++j) {
        const uint32_t o = (uint32_t)(tid + 256 * j) * 16u;
        CPA16(sb + SO_CBUF + o, g_bsplit + o);
    }
    CPA_COMMIT();

    float acc[4][4][4];
    #pragma unroll
    for (int a = 0; a < 4; ++a)
        #pragma unroll
        for (int b = 0; b < 4; ++b)
            #pragma unroll
            for (int c = 0; c < 4; ++c) acc[a][b][c] = 0.f;

    const uint32_t laneoff = (uint32_t)nw * 1536u
        + (uint32_t)((lane & 7) + ((lane >> 4) << 3)) * 48u
        + (uint32_t)((lane >> 3) & 1) * 16u;
    const int r0 = lane >> 2, c0 = (lane & 3) * 2;

    for (int kc = 0; kc < NKC; ++kc) {
        const int b = kc & 1;
        __syncthreads();

        if (kc + 1 < NKC) {
            const unsigned char* sg = g_bsplit + (size_t)(kc + 1) * BUFB;
            const uint32_t dstb = sb + SO_CBUF + (uint32_t)(b ^ 1) * BUFB;
            #pragma unroll
            for (int j = 0; j < 3; ++j) {
                const uint32_t o = (uint32_t)(tid + 256 * j) * 16u;
                CPA16(dstb + o, sg + o);
            }
            CPA_COMMIT();
            const float4 v = *(const float4*)(src + (size_t)xrow * H + (kc + 1) * 16 + xc4);
            *(float4*)&Xs[(b ^ 1) * XS_HALF + xrow * 20 + xc4] = v;
        }

        if (kc + 1 < NKC) CPA_WAIT(1); else CPA_WAIT(0);
        __syncthreads();

        // bf16-hi of X chunk kc -> A fragments
        uint32_t ah[16];
        const float* xbuf = &Xs[b * XS_HALF];
        #pragma unroll
        for (int mt = 0; mt < 4; ++mt)
            #pragma unroll
            for (int i = 0; i < 4; ++i) {
                const int rr = mt * 16 + r0 + (i & 1) * 8;
                const float2 v = *(const float2*)&xbuf[rr * 20 + c0 + (i >> 1) * 8];
                CVT2(ah[mt * 4 + i], v.y, v.x);
            }

        const uint32_t bb = sb + SO_CBUF + (uint32_t)b * BUFB;
        uint32_t b0, b1, b2, b3, b4, b5, b6, b7;
        LDSM4(b0, b1, b2, b3, bb + 0 * 768 + laneoff);
        LDSM4(b4, b5, b6, b7, bb + 1 * 768 + laneoff);
        #pragma unroll
        for (int mt = 0; mt < 4; ++mt) {
            MMA4(acc[mt][0], ah[mt*4+0], ah[mt*4+1], ah[mt*4+2], ah[mt*4+3], b0, b1);
            MMA4(acc[mt][1], ah[mt*4+0], ah[mt*4+1], ah[mt*4+2], ah[mt*4+3], b2, b3);
            MMA4(acc[mt][2], ah[mt*4+0], ah[mt*4+1], ah[mt*4+2], ah[mt*4+3], b4, b5);
            MMA4(acc[mt][3], ah[mt*4+0], ah[mt*4+1], ah[mt*4+2], ah[mt*4+3], b6, b7);
        }
    }

    // ---------------- epilogue: screen -> candidates -> exact rescore ------
    float* csq_s  = (float*)(smem + SO_CSQ);
    float* wval   = (float*)(smem + SO_WVAL);
    float* rmin   = (float*)(smem + SO_RMIN);
    int*   cnt    = (int*)(smem + SO_CNT);
    int*   cand   = (int*)(smem + SO_CAND);
    int*   idxs   = (int*)(smem + SO_IDX);

    __syncthreads();
    csq_s[tid] = g_csq[tid];
    if (tid < MROWS) cnt[tid] = 0;
    __syncthreads();

    // pass 1: per-warp min of screened distance per row
    #pragma unroll
    for (int mt = 0; mt < 4; ++mt)
        #pragma unroll
        for (int h = 0; h < 2; ++h) {
            const int row = mt * 16 + r0 + h * 8;
            float bv = 3.4e38f;
            #pragma unroll
            for (int nt = 0; nt < 4; ++nt) {
                const int col = nw * 32 + nt * 8 + c0;
                const float d0 = csq_s[col]     - 2.0f * acc[mt][nt][2*h];
                const float d1 = csq_s[col + 1] - 2.0f * acc[mt][nt][2*h+1];
                bv = fminf(bv, fminf(d0, d1));
            }
            bv = fminf(bv, __shfl_xor_sync(0xffffffffu, bv, 1));
            bv = fminf(bv, __shfl_xor_sync(0xffffffffu, bv, 2));
            if ((lane & 3) == 0) wval[row * 8 + nw] = bv;
        }
    __syncthreads();
    if (tid < MROWS) {
        float m = wval[tid * 8];
        #pragma unroll
        for (int w = 1; w < 8; ++w) m = fminf(m, wval[tid * 8 + w]);
        rmin[tid] = m;
    }
    __syncthreads();

    // pass 2: append candidates within MARGIN of the screened min
    #pragma unroll
    for (int mt = 0; mt < 4; ++mt)
        #pragma unroll
        for (int h = 0; h < 2; ++h) {
            const int row = mt * 16 + r0 + h * 8;
            const float thr = rmin[row] + MARGIN;
            #pragma unroll
            for (int nt = 0; nt < 4; ++nt) {
                const int col = nw * 32 + nt * 8 + c0;
                const float d0 = csq_s[col]     - 2.0f * acc[mt][nt][2*h];
                const float d1 = csq_s[col + 1] - 2.0f * acc[mt][nt][2*h+1];
                if (d0 <= thr) {
                    const int p = atomicAdd(&cnt[row], 1);
                    if (p < NCAND) cand[row * NCAND + p] = col;
                }
                if (d1 <= thr) {
                    const int p = atomicAdd(&cnt[row], 1);
                    if (p < NCAND) cand[row * NCAND + p] = col + 1;
                }
            }
        }
    __syncthreads();

    // rescore: warp nw owns rows nw*8..nw*8+7; exact fp32 distance
    const float4* cb4 = (const float4*)cb;
    for (int rr = 0; rr < 8; ++rr) {
        const int row = nw * 8 + rr;
        int n = cnt[row]; if (n > NCAND) n = NCAND;
        int winner;
        if (n <= 1) {
            winner = (n == 1) ? cand[row * NCAND] : 0;
        } else {
            float4 xr[8];
            const float4* xp = (const float4*)(src + (size_t)row * H);
            #pragma unroll
            for (int t = 0; t < 8; ++t) xr[t] = __ldg(xp + lane + 32 * t);
            float best = 3.4e38f; int bi = CODES;
            for (int j = 0; j < n; ++j) {
                const int c = cand[row * NCAND + j];
                float p = 0.f;
                #pragma unroll
                for (int t = 0; t < 8; ++t) {
                    const float4 cv = __ldg(cb4 + (size_t)c * (H / 4) + lane + 32 * t);
                    p += xr[t].x * cv.x + xr[t].y * cv.y
                       + xr[t].z * cv.z + xr[t].w * cv.w;
                }
                #pragma unroll
                for (int o = 16; o; o >>= 1) p += __shfl_xor_sync(0xffffffffu, p, o);
                const float d = csq_s[c] - 2.0f * p;
                if (d < best || (d == best && c < bi)) { best = d; bi = c; }
            }
            winner = bi;
        }
        if (lane == 0) idxs[row] = winner;
    }
    __syncthreads();

    // gather winning codebook rows, apply sparsity mask, write coalesced
    float4* o4 = (float4*)out + (size_t)bid * MROWS * (H / 4);
    for (int r = 0; r < MROWS; ++r) {
        const int idx = idxs[r];
        const float sc = (csq_s[idx] > 0.01f) ? 1.0f : 0.0f;   // ||c|| > 0.1
        float4 v = cb4[(size_t)idx * (H / 4) + tid];
        v.x *= sc; v.y *= sc; v.z *= sc; v.w *= sc;
        o4[(size_t)r * (H / 4) + tid] = v;
    }
}

// ---------------------------------------------------------------- launch
extern "C" void kernel_launch(void* const* d_in, const int* in_sizes, int n_in,
                              void* d_out, int out_size) {
    const float* keys     = (const float*)d_in[0];
    const float* values   = (const float*)d_in[1];
    const float* codebook = (const float*)d_in[2];
    float* out = (float*)d_out;
    (void)in_sizes; (void)n_in; (void)out_size;

    cudaFuncSetAttribute(vq_kernel, cudaFuncAttributeMaxDynamicSharedMemorySize, SMEM_TOTAL);
    csq_kernel<<<CODES, 256>>>(codebook);
    bprep_kernel<<<CODES, 256>>>(codebook);
    vq_kernel<<<512, 256, SMEM_TOTAL>>>(keys, values, codebook, out);
}

// round 11
// speedup vs baseline: 3.9957x; 1.2277x over previous
#include <cuda_runtime.h>
#include <cuda_bf16.h>
#include <cstdint>

// FastVCompressor v5: bf16 HMMA screening + exact fp32 rescore.
// vs v4: X prefetch moved to cp.async (kills per-chunk LDG->STS long-scoreboard
// stall), single __syncthreads per chunk.
//   keys   [4,4096,1024] f32 = d_in[0]
//   values [4,4096,1024] f32 = d_in[1]
//   codebook [256,1024]  f32 = d_in[2]
//   out = keys_c ++ values_c (32M floats)

#define H      1024
#define CODES  256
#define MROWS  64          // rows per CTA
#define NKC    64          // k16 chunks
#define BUFB   12288       // one chunk of bf16-hi codebook: 256 codes * 48B
#define NCAND  24
#define MARGIN 2.0f        // ~25 sigma of bf16 screening error

// ---- smem layout ----
#define SO_IDX    0                      // 64 ints: final winner per row
#define SO_CNT    256                    // 64 ints: candidate counts
#define SO_RMIN   512                    // 64 floats: screened min per row
#define SO_CSQ    768                    // 256 floats
#define SO_WVAL   1792                   // 64*8 floats: per-warp row mins
#define SO_CAND   3840                   // 64*24 ints = 6144
#define SO_CBUF   9984                   // 2*BUFB = 24576 (128B aligned)
#define SO_XS     34560                  // Xs[2][64][20] f32 = 10240
#define XS_HALF   1280
#define SMEM_TOTAL 44800

__device__ float g_csq[CODES];
__device__ __align__(128) unsigned char g_bsplit[NKC * BUFB];   // 768 KB (L2-resident)

// ---------------------------------------------------------------- helpers
static __device__ __forceinline__ uint32_t smem_u32(const void* p) {
    uint32_t a;
    asm("{ .reg .u64 t; cvta.to.shared.u64 t, %1; cvt.u32.u64 %0, t; }"
        : "=r"(a) : "l"(p));
    return a;
}

#define CPA16(dst, src) \
    asm volatile("cp.async.cg.shared.global [%0], [%1], 16;" \
                 :: "r"(dst), "l"(src) : "memory")
#define CPA_COMMIT() asm volatile("cp.async.commit_group;" ::: "memory")
#define CPA_WAIT0()  asm volatile("cp.async.wait_group 0;" ::: "memory")

#define LDSM4(r0, r1, r2, r3, addr)                                             \
    asm volatile("ldmatrix.sync.aligned.m8n8.x4.shared.b16 {%0,%1,%2,%3}, [%4];" \
        : "=r"(r0), "=r"(r1), "=r"(r2), "=r"(r3) : "r"(addr))

#define MMA4(c, a0, a1, a2, a3, b0, b1)                                         \
    asm volatile("mma.sync.aligned.m16n8k16.row.col.f32.bf16.bf16.f32 "         \
        "{%0,%1,%2,%3}, {%4,%5,%6,%7}, {%8,%9}, {%0,%1,%2,%3};"                 \
        : "+f"((c)[0]), "+f"((c)[1]), "+f"((c)[2]), "+f"((c)[3])                \
        : "r"(a0), "r"(a1), "r"(a2), "r"(a3), "r"(b0), "r"(b1))

#define CVT2(d, hi, lo) \
    asm("cvt.rn.bf16x2.f32 %0, %1, %2;" : "=r"(d) : "f"(hi), "f"(lo))

// ---------------------------------------------------------------- prep: c_sq
__global__ void csq_kernel(const float* __restrict__ cb) {
    const int c = blockIdx.x;
    const float4 v = ((const float4*)(cb + (size_t)c * H))[threadIdx.x];
    float s = v.x * v.x + v.y * v.y + v.z * v.z + v.w * v.w;
    #pragma unroll
    for (int o = 16; o; o >>= 1) s += __shfl_xor_sync(0xffffffffu, s, o);
    __shared__ float ws[8];
    if ((threadIdx.x & 31) == 0) ws[threadIdx.x >> 5] = s;
    __syncthreads();
    if (threadIdx.x == 0) {
        float t = 0.f;
        #pragma unroll
        for (int i = 0; i < 8; ++i) t += ws[i];
        g_csq[c] = t;
    }
}

// ------------------------------------------- prep: codebook bf16-hi, 48B rows
__global__ void bprep_kernel(const float* __restrict__ cb) {
    const int code = blockIdx.x;
    const float4 v = ((const float4*)(cb + (size_t)code * H))[threadIdx.x];
    const float f[4] = {v.x, v.y, v.z, v.w};
    #pragma unroll
    for (int e = 0; e < 4; ++e) {
        const int k = threadIdx.x * 4 + e;
        *(__nv_bfloat16*)(g_bsplit + (size_t)(k >> 4) * BUFB + code * 48 + (k & 15) * 2)
            = __float2bfloat16(f[e]);
    }
}

// ---------------------------------------------------------------- main VQ
__global__ __launch_bounds__(256, 2) void vq_kernel(
    const float* __restrict__ keys, const float* __restrict__ values,
    const float* __restrict__ cb, float* __restrict__ out)
{
    extern __shared__ char smem[];
    const uint32_t sb = smem_u32(smem);
    const int tid = threadIdx.x, lane = tid & 31, nw = tid >> 5;
    const int bid = blockIdx.x;

    const float* src = (bid < 256) ? keys   + (size_t)bid * MROWS * H
                                   : values + (size_t)(bid - 256) * MROWS * H;

    const int xrow = tid >> 2, xc4 = (tid & 3) * 4;
    // byte offset of this thread's 16B X slot within an Xs buffer (stride 20 f32)
    const uint32_t xs_off = (uint32_t)(xrow * 20 + xc4) * 4u;

    // prologue: chunk 0 (B: 3x16B, X: 1x16B per thread) via cp.async
    #pragma unroll
    for (int j = 0; j < 3; ++j) {
        const uint32_t o = (uint32_t)(tid + 256 * j) * 16u;
        CPA16(sb + SO_CBUF + o, g_bsplit + o);
    }
    CPA16(sb + SO_XS + xs_off, src + (size_t)xrow * H + xc4);
    CPA_COMMIT();

    float acc[4][4][4];
    #pragma unroll
    for (int a = 0; a < 4; ++a)
        #pragma unroll
        for (int b = 0; b < 4; ++b)
            #pragma unroll
            for (int c = 0; c < 4; ++c) acc[a][b][c] = 0.f;

    const uint32_t laneoff = (uint32_t)nw * 1536u
        + (uint32_t)((lane & 7) + ((lane >> 4) << 3)) * 48u
        + (uint32_t)((lane >> 3) & 1) * 16u;
    const int r0 = lane >> 2, c0 = (lane & 3) * 2;

    for (int kc = 0; kc < NKC; ++kc) {
        const int b = kc & 1;
        CPA_WAIT0();        // this thread's copies for chunk kc (buf b) done
        __syncthreads();    // all threads' copies visible; prev compute done

        if (kc + 1 < NKC) {  // prefetch chunk kc+1 -> buf b^1
            const unsigned char* sg = g_bsplit + (size_t)(kc + 1) * BUFB;
            const uint32_t dstb = sb + SO_CBUF + (uint32_t)(b ^ 1) * BUFB;
            #pragma unroll
            for (int j = 0; j < 3; ++j) {
                const uint32_t o = (uint32_t)(tid + 256 * j) * 16u;
                CPA16(dstb + o, sg + o);
            }
            CPA16(sb + SO_XS + (uint32_t)(b ^ 1) * (XS_HALF * 4) + xs_off,
                  src + (size_t)xrow * H + (kc + 1) * 16 + xc4);
            CPA_COMMIT();
        }

        // B fragments first (feed tensor early)
        const uint32_t bb = sb + SO_CBUF + (uint32_t)b * BUFB;
        uint32_t b0, b1, b2, b3, b4, b5, b6, b7;
        LDSM4(b0, b1, b2, b3, bb + 0 * 768 + laneoff);
        LDSM4(b4, b5, b6, b7, bb + 1 * 768 + laneoff);

        // bf16-hi of X chunk kc -> A fragments
        uint32_t ah[16];
        const float* xbuf = (const float*)(smem + SO_XS) + b * XS_HALF;
        #pragma unroll
        for (int mt = 0; mt < 4; ++mt)
            #pragma unroll
            for (int i = 0; i < 4; ++i) {
                const int rr = mt * 16 + r0 + (i & 1) * 8;
                const float2 v = *(const float2*)&xbuf[rr * 20 + c0 + (i >> 1) * 8];
                CVT2(ah[mt * 4 + i], v.y, v.x);
            }

        #pragma unroll
        for (int mt = 0; mt < 4; ++mt) {
            MMA4(acc[mt][0], ah[mt*4+0], ah[mt*4+1], ah[mt*4+2], ah[mt*4+3], b0, b1);
            MMA4(acc[mt][1], ah[mt*4+0], ah[mt*4+1], ah[mt*4+2], ah[mt*4+3], b2, b3);
            MMA4(acc[mt][2], ah[mt*4+0], ah[mt*4+1], ah[mt*4+2], ah[mt*4+3], b4, b5);
            MMA4(acc[mt][3], ah[mt*4+0], ah[mt*4+1], ah[mt*4+2], ah[mt*4+3], b6, b7);
        }
    }

    // ---------------- epilogue: screen -> candidates -> exact rescore ------
    float* csq_s  = (float*)(smem + SO_CSQ);
    float* wval   = (float*)(smem + SO_WVAL);
    float* rmin   = (float*)(smem + SO_RMIN);
    int*   cnt    = (int*)(smem + SO_CNT);
    int*   cand   = (int*)(smem + SO_CAND);
    int*   idxs   = (int*)(smem + SO_IDX);

    __syncthreads();
    csq_s[tid] = g_csq[tid];
    if (tid < MROWS) cnt[tid] = 0;
    __syncthreads();

    // pass 1: per-warp min of screened distance per row
    #pragma unroll
    for (int mt = 0; mt < 4; ++mt)
        #pragma unroll
        for (int h = 0; h < 2; ++h) {
            const int row = mt * 16 + r0 + h * 8;
            float bv = 3.4e38f;
            #pragma unroll
            for (int nt = 0; nt < 4; ++nt) {
                const int col = nw * 32 + nt * 8 + c0;
                const float d0 = csq_s[col]     - 2.0f * acc[mt][nt][2*h];
                const float d1 = csq_s[col + 1] - 2.0f * acc[mt][nt][2*h+1];
                bv = fminf(bv, fminf(d0, d1));
            }
            bv = fminf(bv, __shfl_xor_sync(0xffffffffu, bv, 1));
            bv = fminf(bv, __shfl_xor_sync(0xffffffffu, bv, 2));
            if ((lane & 3) == 0) wval[row * 8 + nw] = bv;
        }
    __syncthreads();
    if (tid < MROWS) {
        float m = wval[tid * 8];
        #pragma unroll
        for (int w = 1; w < 8; ++w) m = fminf(m, wval[tid * 8 + w]);
        rmin[tid] = m;
    }
    __syncthreads();

    // pass 2: append candidates within MARGIN of the screened min
    #pragma unroll
    for (int mt = 0; mt < 4; ++mt)
        #pragma unroll
        for (int h = 0; h < 2; ++h) {
            const int row = mt * 16 + r0 + h * 8;
            const float thr = rmin[row] + MARGIN;
            #pragma unroll
            for (int nt = 0; nt < 4; ++nt) {
                const int col = nw * 32 + nt * 8 + c0;
                const float d0 = csq_s[col]     - 2.0f * acc[mt][nt][2*h];
                const float d1 = csq_s[col + 1] - 2.0f * acc[mt][nt][2*h+1];
                if (d0 <= thr) {
                    const int p = atomicAdd(&cnt[row], 1);
                    if (p < NCAND) cand[row * NCAND + p] = col;
                }
                if (d1 <= thr) {
                    const int p = atomicAdd(&cnt[row], 1);
                    if (p < NCAND) cand[row * NCAND + p] = col + 1;
                }
            }
        }
    __syncthreads();

    // rescore: warp nw owns rows nw*8..nw*8+7; exact fp32 distance
    const float4* cb4 = (const float4*)cb;
    for (int rr = 0; rr < 8; ++rr) {
        const int row = nw * 8 + rr;
        int n = cnt[row]; if (n > NCAND) n = NCAND;
        int winner;
        if (n <= 1) {
            winner = (n == 1) ? cand[row * NCAND] : 0;
        } else {
            float4 xr[8];
            const float4* xp = (const float4*)(src + (size_t)row * H);
            #pragma unroll
            for (int t = 0; t < 8; ++t) xr[t] = __ldg(xp + lane + 32 * t);
            float best = 3.4e38f; int bi = CODES;
            for (int j = 0; j < n; ++j) {
                const int c = cand[row * NCAND + j];
                float p = 0.f;
                #pragma unroll
                for (int t = 0; t < 8; ++t) {
                    const float4 cv = __ldg(cb4 + (size_t)c * (H / 4) + lane + 32 * t);
                    p += xr[t].x * cv.x + xr[t].y * cv.y
                       + xr[t].z * cv.z + xr[t].w * cv.w;
                }
                #pragma unroll
                for (int o = 16; o; o >>= 1) p += __shfl_xor_sync(0xffffffffu, p, o);
                const float d = csq_s[c] - 2.0f * p;
                if (d < best || (d == best && c < bi)) { best = d; bi = c; }
            }
            winner = bi;
        }
        if (lane == 0) idxs[row] = winner;
    }
    __syncthreads();

    // gather winning codebook rows, apply sparsity mask, write coalesced
    float4* o4 = (float4*)out + (size_t)bid * MROWS * (H / 4);
    for (int r = 0; r < MROWS; ++r) {
        const int idx = idxs[r];
        const float sc = (csq_s[idx] > 0.01f) ? 1.0f : 0.0f;   // ||c|| > 0.1
        float4 v = cb4[(size_t)idx * (H / 4) + tid];
        v.x *= sc; v.y *= sc; v.z *= sc; v.w *= sc;
        o4[(size_t)r * (H / 4) + tid] = v;
    }
}

// ---------------------------------------------------------------- launch
extern "C" void kernel_launch(void* const* d_in, const int* in_sizes, int n_in,
                              void* d_out, int out_size) {
    const float* keys     = (const float*)d_in[0];
    const float* values   = (const float*)d_in[1];
    const float* codebook = (const float*)d_in[2];
    float* out = (float*)d_out;
    (void)in_sizes; (void)n_in; (void)out_size;

    cudaFuncSetAttribute(vq_kernel, cudaFuncAttributeMaxDynamicSharedMemorySize, SMEM_TOTAL);
    csq_kernel<<<CODES, 256>>>(codebook);
    bprep_kernel<<<CODES, 256>>>(codebook);
    vq_kernel<<<512, 256, SMEM_TOTAL>>>(keys, values, codebook, out);
}